// round 2
// baseline (speedup 1.0000x reference)
#include <cuda_runtime.h>
#include <cstdint>

// Problem dims
#define M_ROWS 4096     // S*B = 8*512
#define DIN    60       // 10 digits + 50 styles
#define HN     512
#define BT     160      // bottleneck
#define P_DIM  12288    // 3*64*64
#define GROUPS 192      // 3*64  (output per row; each sums 64 pixels)

// Scratch for t = selu(h@W1+b1): 4096 x 160 fp32 (2.6 MB device global, no allocs)
__device__ float g_t[M_ROWS * BT];

// ---------------- packed fp32x2 helpers (sm_100a) ----------------
__device__ __forceinline__ unsigned long long dup2(float a) {
    unsigned long long r;
    asm("mov.b64 %0, {%1, %1};" : "=l"(r) : "f"(a));
    return r;
}
__device__ __forceinline__ void ffma2(unsigned long long &c, unsigned long long a, unsigned long long b) {
    asm("fma.rn.f32x2 %0, %1, %2, %0;" : "+l"(c) : "l"(a), "l"(b));
}
__device__ __forceinline__ void unpack2(unsigned long long v, float &lo, float &hi) {
    asm("mov.b64 {%0, %1}, %2;" : "=f"(lo), "=f"(hi) : "l"(v));
}

// BCE-with-logits: -(log(sigmoid(z))*img + log(1-sigmoid(z))*(1-img)) = softplus(z) - img*z
__device__ __forceinline__ float lossf(float z, float img) {
    float e = __expf(-fabsf(z));
    return fmaxf(z, 0.0f) + __logf(1.0f + e) - img * z;
}

// ================= Kernel 1: t = selu(relu(x@W_h+b_h)@W1+b1) =================
// 8 rows per block, 256 threads. 512 blocks.
__global__ __launch_bounds__(256) void k_hidden(
    const float* __restrict__ digits, const float* __restrict__ styles,
    const float* __restrict__ W_h, const float* __restrict__ b_h,
    const float* __restrict__ W1, const float* __restrict__ b1)
{
    __shared__ float x_s[8][DIN];
    __shared__ float h_s[8][HN];
    const int tid = threadIdx.x;
    const int row0 = blockIdx.x * 8;

    // Phase A: gather concat(digits, styles) for 8 rows
    for (int i = tid; i < 8 * DIN; i += 256) {
        int r = i / DIN, c = i % DIN;
        int row = row0 + r;
        x_s[r][c] = (c < 10) ? digits[row * 10 + c] : styles[row * 50 + (c - 10)];
    }
    __syncthreads();

    // Phase B: h = relu(x @ W_h + b_h), float4 over j
    for (int idx = tid; idx < 8 * 128; idx += 256) {
        int r = idx >> 7;
        int j = (idx & 127) * 4;
        float4 acc = *(const float4*)&b_h[j];
        #pragma unroll 6
        for (int k = 0; k < DIN; ++k) {
            float4 w = *(const float4*)&W_h[k * HN + j];
            float xv = x_s[r][k];
            acc.x = fmaf(xv, w.x, acc.x);
            acc.y = fmaf(xv, w.y, acc.y);
            acc.z = fmaf(xv, w.z, acc.z);
            acc.w = fmaf(xv, w.w, acc.w);
        }
        acc.x = fmaxf(acc.x, 0.f); acc.y = fmaxf(acc.y, 0.f);
        acc.z = fmaxf(acc.z, 0.f); acc.w = fmaxf(acc.w, 0.f);
        *(float4*)&h_s[r][j] = acc;
    }
    __syncthreads();

    // Phase C: t = selu(h @ W1 + b1); thread j computes all 8 rows
    if (tid < BT) {
        const int j = tid;
        float acc[8];
        const float bj = b1[j];
        #pragma unroll
        for (int r = 0; r < 8; ++r) acc[r] = bj;
        #pragma unroll 4
        for (int k = 0; k < HN; ++k) {
            float w = W1[k * BT + j];
            #pragma unroll
            for (int r = 0; r < 8; ++r) acc[r] = fmaf(h_s[r][k], w, acc[r]);
        }
        const float scale = 1.0507009873554805f;
        const float alpha = 1.6732632423543772f;
        #pragma unroll
        for (int r = 0; r < 8; ++r) {
            float v = acc[r];
            float s = (v > 0.f) ? scale * v : scale * alpha * expm1f(v);
            g_t[(row0 + r) * BT + j] = s;
        }
    }
}

// ====== Kernel 2: z = t@W2+b2 ; loss = softplus(z)-img*z ; 64-wide sums ======
// Tile: 128 rows x 128 cols, K-chunks of 16. 256 threads (16x16), 8x8/thread
// via packed fp32x2 FFMA. Grid (96, 32) = 3072 blocks.
#define RT  128
#define JT  128
#define KC  16
#define RTP 132   // pad: conflict-free strided access, keeps 16B alignment

__global__ __launch_bounds__(256, 2) void k_decode(
    const float* __restrict__ images,
    const float* __restrict__ W2, const float* __restrict__ b2,
    float* __restrict__ out)
{
    __shared__ float t_s[KC][RTP];   // transposed: t_s[k][r]
    __shared__ float w_s[KC][JT];

    const int tid = threadIdx.x;
    const int tx = tid & 15, ty = tid >> 4;
    const int j0   = blockIdx.x * JT;
    const int row0 = blockIdx.y * RT;

    unsigned long long c[8][4];
    #pragma unroll
    for (int r = 0; r < 8; ++r)
        #pragma unroll
        for (int q = 0; q < 4; ++q) c[r][q] = 0ull;

    for (int kc0 = 0; kc0 < BT; kc0 += KC) {
        // load t chunk (transpose into t_s[k][r]); float4 along k from global
        #pragma unroll
        for (int it = 0; it < 2; ++it) {
            int idx = tid + it * 256;          // 512 items
            int r  = idx >> 2;                 // 0..127
            int kq = (idx & 3) * 4;            // 0,4,8,12
            float4 v = *(const float4*)&g_t[(row0 + r) * BT + kc0 + kq];
            t_s[kq + 0][r] = v.x;
            t_s[kq + 1][r] = v.y;
            t_s[kq + 2][r] = v.z;
            t_s[kq + 3][r] = v.w;
        }
        // load W2 chunk [16][128], coalesced float4
        #pragma unroll
        for (int it = 0; it < 2; ++it) {
            int idx = tid + it * 256;          // 512 items
            int k  = idx >> 5;
            int jq = (idx & 31) * 4;
            *(float4*)&w_s[k][jq] =
                *(const float4*)&W2[(size_t)(kc0 + k) * P_DIM + j0 + jq];
        }
        __syncthreads();

        #pragma unroll
        for (int k = 0; k < KC; ++k) {
            float4 A0 = *(const float4*)&t_s[k][4 * ty];        // rows 4ty..+3
            float4 A1 = *(const float4*)&t_s[k][64 + 4 * ty];   // rows 64+4ty..+3
            ulonglong2 B0 = *(const ulonglong2*)&w_s[k][4 * tx];       // j pairs
            ulonglong2 B1 = *(const ulonglong2*)&w_s[k][64 + 4 * tx];
            unsigned long long aa;
            aa = dup2(A0.x); ffma2(c[0][0],aa,B0.x); ffma2(c[0][1],aa,B0.y); ffma2(c[0][2],aa,B1.x); ffma2(c[0][3],aa,B1.y);
            aa = dup2(A0.y); ffma2(c[1][0],aa,B0.x); ffma2(c[1][1],aa,B0.y); ffma2(c[1][2],aa,B1.x); ffma2(c[1][3],aa,B1.y);
            aa = dup2(A0.z); ffma2(c[2][0],aa,B0.x); ffma2(c[2][1],aa,B0.y); ffma2(c[2][2],aa,B1.x); ffma2(c[2][3],aa,B1.y);
            aa = dup2(A0.w); ffma2(c[3][0],aa,B0.x); ffma2(c[3][1],aa,B0.y); ffma2(c[3][2],aa,B1.x); ffma2(c[3][3],aa,B1.y);
            aa = dup2(A1.x); ffma2(c[4][0],aa,B0.x); ffma2(c[4][1],aa,B0.y); ffma2(c[4][2],aa,B1.x); ffma2(c[4][3],aa,B1.y);
            aa = dup2(A1.y); ffma2(c[5][0],aa,B0.x); ffma2(c[5][1],aa,B0.y); ffma2(c[5][2],aa,B1.x); ffma2(c[5][3],aa,B1.y);
            aa = dup2(A1.z); ffma2(c[6][0],aa,B0.x); ffma2(c[6][1],aa,B0.y); ffma2(c[6][2],aa,B1.x); ffma2(c[6][3],aa,B1.y);
            aa = dup2(A1.w); ffma2(c[7][0],aa,B0.x); ffma2(c[7][1],aa,B0.y); ffma2(c[7][2],aa,B1.x); ffma2(c[7][3],aa,B1.y);
        }
        __syncthreads();
    }

    // Epilogue: bias + BCE-with-logits + sum over each 64-wide group
    float4 b2lo = *(const float4*)&b2[j0 + 4 * tx];
    float4 b2hi = *(const float4*)&b2[j0 + 64 + 4 * tx];
    const int gbase = j0 >> 6;   // 2*blockIdx.x

    #pragma unroll
    for (int ri = 0; ri < 8; ++ri) {
        int row = row0 + ((ri < 4) ? (4 * ty + ri) : (60 + 4 * ty + ri)); // 64+4ty+(ri-4)
        const float* imrow = images + (size_t)row * P_DIM + j0;
        float4 im0 = *(const float4*)&imrow[4 * tx];
        float4 im1 = *(const float4*)&imrow[64 + 4 * tx];

        float z0, z1, p0 = 0.f, p1 = 0.f;
        unpack2(c[ri][0], z0, z1);
        p0 += lossf(z0 + b2lo.x, im0.x) + lossf(z1 + b2lo.y, im0.y);
        unpack2(c[ri][1], z0, z1);
        p0 += lossf(z0 + b2lo.z, im0.z) + lossf(z1 + b2lo.w, im0.w);
        unpack2(c[ri][2], z0, z1);
        p1 += lossf(z0 + b2hi.x, im1.x) + lossf(z1 + b2hi.y, im1.y);
        unpack2(c[ri][3], z0, z1);
        p1 += lossf(z0 + b2hi.z, im1.z) + lossf(z1 + b2hi.w, im1.w);

        // reduce across tx (xor < 16 stays within the 16-lane half-warp)
        #pragma unroll
        for (int m = 8; m >= 1; m >>= 1) {
            p0 += __shfl_xor_sync(0xffffffffu, p0, m);
            p1 += __shfl_xor_sync(0xffffffffu, p1, m);
        }
        if (tx == 0) {
            out[(size_t)row * GROUPS + gbase]     = p0;
            out[(size_t)row * GROUPS + gbase + 1] = p1;
        }
    }
}

// ============================== launcher ==============================
extern "C" void kernel_launch(void* const* d_in, const int* in_sizes, int n_in,
                              void* d_out, int out_size) {
    // Map inputs by element count (robust to metadata ordering); all distinct.
    const float *digits = nullptr, *styles = nullptr, *images = nullptr;
    const float *W_h = nullptr, *b_h = nullptr, *W1 = nullptr, *b1 = nullptr;
    const float *W2 = nullptr, *b2 = nullptr;
    for (int i = 0; i < n_in; ++i) {
        const float* p = (const float*)d_in[i];
        switch (in_sizes[i]) {
            case 8 * 512 * 10:        digits = p; break;   // 40960
            case 8 * 512 * 50:        styles = p; break;   // 204800
            case 8 * 512 * P_DIM:     images = p; break;   // 50331648
            case DIN * HN:            W_h    = p; break;   // 30720
            case HN:                  b_h    = p; break;   // 512
            case HN * BT:             W1     = p; break;   // 81920
            case BT:                  b1     = p; break;   // 160
            case BT * P_DIM:          W2     = p; break;   // 1966080
            case P_DIM:               b2     = p; break;   // 12288
            default: break;
        }
    }
    float* out = (float*)d_out;

    k_hidden<<<M_ROWS / 8, 256>>>(digits, styles, W_h, b_h, W1, b1);
    dim3 grid(P_DIM / JT, M_ROWS / RT);   // (96, 32)
    k_decode<<<grid, 256>>>(images, W2, b2, out);
}

// round 8
// speedup vs baseline: 1.7112x; 1.7112x over previous
#include <cuda_runtime.h>
#include <cstdint>

// Problem dims
#define M_ROWS 4096
#define DIN    60
#define HN     512
#define BT     160
#define P_DIM  12288
#define GROUPS 192

// decode tiling
#define RT 128
#define NT 128
#define KC 32
#define NCHUNK 5      // 160/32

// smem (floats) for k_decode
#define A_STRIDE 36           // 32 + 4 pad
#define B_STRIDE 136          // 128 + 8 pad
#define A_BUF_F  (128 * A_STRIDE)          // 4608
#define B_OFF_F  (2 * A_BUF_F)             // 9216
#define B_BUF_F  (32 * B_STRIDE)           // 4352
#define RED_OFF_F (B_OFF_F + 2 * B_BUF_F)  // 17920
#define SMEM_F   (RED_OFF_F + 128 * 4)     // 18432 floats
#define SMEM_BYTES (SMEM_F * 4)            // 73728

__device__ float g_t[M_ROWS * BT];

// ---------------- helpers ----------------
__device__ __forceinline__ uint32_t smem_u32(const void* p) {
    uint32_t a;
    asm("{ .reg .u64 t; cvta.to.shared.u64 t, %1; cvt.u32.u64 %0, t; }" : "=r"(a) : "l"(p));
    return a;
}
__device__ __forceinline__ void cpa16(uint32_t dst, const void* src) {
    asm volatile("cp.async.cg.shared.global [%0], [%1], 16;" :: "r"(dst), "l"(src));
}
__device__ __forceinline__ void cp_commit() {
    asm volatile("cp.async.commit_group;" ::: "memory");
}
__device__ __forceinline__ void cp_wait1() {
    asm volatile("cp.async.wait_group 1;" ::: "memory");
}
__device__ __forceinline__ void cp_wait0() {
    asm volatile("cp.async.wait_group 0;" ::: "memory");
}
__device__ __forceinline__ uint32_t to_tf32(float x) {
    uint32_t r;
    asm("cvt.rna.tf32.f32 %0, %1;" : "=r"(r) : "f"(x));
    return r;
}
__device__ __forceinline__ void mma_tf32(float* c, const uint32_t* a, const uint32_t* b) {
    asm volatile(
        "mma.sync.aligned.m16n8k8.row.col.f32.tf32.tf32.f32 "
        "{%0,%1,%2,%3}, {%4,%5,%6,%7}, {%8,%9}, {%0,%1,%2,%3};"
        : "+f"(c[0]), "+f"(c[1]), "+f"(c[2]), "+f"(c[3])
        : "r"(a[0]), "r"(a[1]), "r"(a[2]), "r"(a[3]), "r"(b[0]), "r"(b[1]));
}
// packed fp32x2
__device__ __forceinline__ unsigned long long dup2(float a) {
    unsigned long long r;
    asm("mov.b64 %0, {%1, %1};" : "=l"(r) : "f"(a));
    return r;
}
__device__ __forceinline__ void ffma2(unsigned long long &c, unsigned long long a, unsigned long long b) {
    asm("fma.rn.f32x2 %0, %1, %2, %0;" : "+l"(c) : "l"(a), "l"(b));
}
__device__ __forceinline__ void unpack2(unsigned long long v, float &lo, float &hi) {
    asm("mov.b64 {%0, %1}, %2;" : "=f"(lo), "=f"(hi) : "l"(v));
}

// BCE-with-logits: softplus(z) - img*z
__device__ __forceinline__ float lossf(float z, float img) {
    float e = __expf(-fabsf(z));
    return fmaxf(z, 0.0f) + __logf(1.0f + e) - img * z;
}

// ================= Kernel 1: t = selu(relu(x@W_h+b_h)@W1+b1) =================
__global__ __launch_bounds__(320) void k_hidden(
    const float* __restrict__ digits, const float* __restrict__ styles,
    const float* __restrict__ W_h, const float* __restrict__ b_h,
    const float* __restrict__ W1, const float* __restrict__ b1)
{
    __shared__ float x_s[8][DIN];
    __shared__ float h2[HN][10];     // [k][row], pad to 10 (40B rows, 8B-aligned pairs)
    __shared__ float part[8][BT];
    const int tid = threadIdx.x;
    const int row0 = blockIdx.x * 8;

    for (int i = tid; i < 8 * DIN; i += 320) {
        int r = i / DIN, c = i % DIN;
        int row = row0 + r;
        x_s[r][c] = (c < 10) ? digits[row * 10 + c] : styles[row * 50 + (c - 10)];
    }
    __syncthreads();

    // Phase B: h = relu(x@W_h+b_h), stored TRANSPOSED into h2[k][r]
    for (int idx = tid; idx < 8 * 128; idx += 320) {
        int r = idx & 7;
        int j = (idx >> 3) * 4;
        float4 acc = *(const float4*)&b_h[j];
        #pragma unroll 6
        for (int k = 0; k < DIN; ++k) {
            float4 w = *(const float4*)&W_h[k * HN + j];
            float xv = x_s[r][k];
            acc.x = fmaf(xv, w.x, acc.x);
            acc.y = fmaf(xv, w.y, acc.y);
            acc.z = fmaf(xv, w.z, acc.z);
            acc.w = fmaf(xv, w.w, acc.w);
        }
        h2[j + 0][r] = fmaxf(acc.x, 0.f);
        h2[j + 1][r] = fmaxf(acc.y, 0.f);
        h2[j + 2][r] = fmaxf(acc.z, 0.f);
        h2[j + 3][r] = fmaxf(acc.w, 0.f);
    }
    __syncthreads();

    // Phase C: packed f32x2 over row-pairs; K split across s=0/1
    {
        const int j = tid % BT;
        const int s = tid / BT;
        unsigned long long acc2[4] = {0ull, 0ull, 0ull, 0ull};
        const int k0 = s * 256;
        #pragma unroll 4
        for (int k = k0; k < k0 + 256; ++k) {
            unsigned long long bb = dup2(W1[k * BT + j]);
            #pragma unroll
            for (int p = 0; p < 4; ++p)
                ffma2(acc2[p], *(const unsigned long long*)&h2[k][2 * p], bb);
        }
        float a[8];
        #pragma unroll
        for (int p = 0; p < 4; ++p) unpack2(acc2[p], a[2 * p], a[2 * p + 1]);
        if (s == 1) {
            #pragma unroll
            for (int r = 0; r < 8; ++r) part[r][j] = a[r];
        }
        __syncthreads();
        if (s == 0) {
            const float scale = 1.0507009873554805f;
            const float alpha = 1.6732632423543772f;
            const float bj = b1[j];
            #pragma unroll
            for (int r = 0; r < 8; ++r) {
                float v = a[r] + part[r][j] + bj;
                float o = (v > 0.f) ? scale * v : scale * alpha * expm1f(v);
                g_t[(row0 + r) * BT + j] = o;
            }
        }
    }
}

// ========== Kernel 2: mma.sync tf32 GEMM (z=t@W2+b2) + fused BCE + 64-sum ==========
__global__ __launch_bounds__(256, 2) void k_decode(
    const float* __restrict__ images,
    const float* __restrict__ W2, const float* __restrict__ b2,
    float* __restrict__ out)
{
    extern __shared__ float smf[];
    const uint32_t sb = smem_u32(smf);
    const int tid  = threadIdx.x;
    const int wid  = tid >> 5;
    const int lane = tid & 31;
    const int r    = lane >> 2;     // 0..7  (A row / B col within frag)
    const int qc   = lane & 3;      // 0..3  (A col / B row within frag)
    const int warp_m = (wid >> 2) * 64;
    const int warp_n = (wid & 3) * 32;
    const int j0   = blockIdx.x * NT;
    const int row0 = blockIdx.y * RT;

    // ---- async loaders ----
    auto issueA = [&](int buf, int kc0) {
        #pragma unroll
        for (int i = 0; i < 4; ++i) {
            int idx = tid + i * 256;        // 1024 segs of 16B: 128 rows x 8 segs
            int rr  = idx >> 3;
            int seg = idx & 7;
            cpa16(sb + (uint32_t)(buf * A_BUF_F + rr * A_STRIDE + seg * 4) * 4,
                  g_t + (size_t)(row0 + rr) * BT + kc0 + seg * 4);
        }
    };
    auto issueB = [&](int buf, int kc0) {
        #pragma unroll
        for (int i = 0; i < 4; ++i) {
            int idx = tid + i * 256;        // 1024 segs of 16B: 32 k x 32 segs (128 n)
            int k   = idx >> 5;
            int seg = idx & 31;
            cpa16(sb + (uint32_t)(B_OFF_F + buf * B_BUF_F + k * B_STRIDE + seg * 4) * 4,
                  W2 + (size_t)(kc0 + k) * P_DIM + j0 + seg * 4);
        }
    };

    float c4[4][4][4];
    #pragma unroll
    for (int mi = 0; mi < 4; ++mi)
        #pragma unroll
        for (int ni = 0; ni < 4; ++ni)
            #pragma unroll
            for (int q = 0; q < 4; ++q) c4[mi][ni][q] = 0.f;

    issueA(0, 0); issueB(0, 0); cp_commit();

    for (int c = 0; c < NCHUNK; ++c) {
        if (c + 1 < NCHUNK) {
            issueA((c + 1) & 1, (c + 1) * KC);
            issueB((c + 1) & 1, (c + 1) * KC);
            cp_commit();
            cp_wait1();
        } else {
            cp_wait0();
        }
        __syncthreads();

        const float* A = smf + (c & 1) * A_BUF_F;
        const float* B = smf + B_OFF_F + (c & 1) * B_BUF_F;
        #pragma unroll
        for (int kk = 0; kk < 4; ++kk) {
            uint32_t a[4][4];
            #pragma unroll
            for (int mi = 0; mi < 4; ++mi) {
                const float* ap = A + (warp_m + mi * 16 + r) * A_STRIDE + kk * 8 + qc;
                a[mi][0] = to_tf32(ap[0]);
                a[mi][1] = to_tf32(ap[8 * A_STRIDE]);
                a[mi][2] = to_tf32(ap[4]);
                a[mi][3] = to_tf32(ap[8 * A_STRIDE + 4]);
            }
            uint32_t b[4][2];
            #pragma unroll
            for (int ni = 0; ni < 4; ++ni) {
                const float* bp = B + (kk * 8 + qc) * B_STRIDE + warp_n + ni * 8 + r;
                b[ni][0] = to_tf32(bp[0]);
                b[ni][1] = to_tf32(bp[4 * B_STRIDE]);
            }
            #pragma unroll
            for (int mi = 0; mi < 4; ++mi)
                #pragma unroll
                for (int ni = 0; ni < 4; ++ni)
                    mma_tf32(c4[mi][ni], a[mi], b[ni]);
        }
        __syncthreads();
    }

    // ---- epilogue: bias + BCE + 64-wide group sums ----
    float* red = smf + RED_OFF_F;
    float2 b2v[4];
    #pragma unroll
    for (int ni = 0; ni < 4; ++ni)
        b2v[ni] = *(const float2*)&b2[j0 + warp_n + ni * 8 + 2 * qc];

    #pragma unroll
    for (int mi = 0; mi < 4; ++mi) {
        const int lr0 = warp_m + mi * 16 + r;        // local row (0..127)
        const float* im0 = images + (size_t)(row0 + lr0) * P_DIM + j0;
        const float* im1 = images + (size_t)(row0 + lr0 + 8) * P_DIM + j0;
        float p0 = 0.f, p1 = 0.f;
        #pragma unroll
        for (int ni = 0; ni < 4; ++ni) {
            const int nc = warp_n + ni * 8 + 2 * qc;
            float2 i0 = *(const float2*)&im0[nc];
            float2 i1 = *(const float2*)&im1[nc];
            p0 += lossf(c4[mi][ni][0] + b2v[ni].x, i0.x) + lossf(c4[mi][ni][1] + b2v[ni].y, i0.y);
            p1 += lossf(c4[mi][ni][2] + b2v[ni].x, i1.x) + lossf(c4[mi][ni][3] + b2v[ni].y, i1.y);
        }
        p0 += __shfl_xor_sync(0xffffffffu, p0, 1);
        p0 += __shfl_xor_sync(0xffffffffu, p0, 2);
        p1 += __shfl_xor_sync(0xffffffffu, p1, 1);
        p1 += __shfl_xor_sync(0xffffffffu, p1, 2);
        if (qc == 0) {
            red[lr0 * 4 + (wid & 3)]       = p0;
            red[(lr0 + 8) * 4 + (wid & 3)] = p1;
        }
    }
    __syncthreads();

    {
        const int row = tid >> 1;
        const int g   = tid & 1;
        float v = red[row * 4 + 2 * g] + red[row * 4 + 2 * g + 1];
        out[(size_t)(row0 + row) * GROUPS + (j0 >> 6) + g] = v;
    }
}

// ============================== launcher ==============================
extern "C" void kernel_launch(void* const* d_in, const int* in_sizes, int n_in,
                              void* d_out, int out_size) {
    const float *digits = nullptr, *styles = nullptr, *images = nullptr;
    const float *W_h = nullptr, *b_h = nullptr, *W1 = nullptr, *b1 = nullptr;
    const float *W2 = nullptr, *b2 = nullptr;
    for (int i = 0; i < n_in; ++i) {
        const float* p = (const float*)d_in[i];
        switch (in_sizes[i]) {
            case 8 * 512 * 10:    digits = p; break;
            case 8 * 512 * 50:    styles = p; break;
            case 8 * 512 * P_DIM: images = p; break;
            case DIN * HN:        W_h    = p; break;
            case HN:              b_h    = p; break;
            case HN * BT:         W1     = p; break;
            case BT:              b1     = p; break;
            case BT * P_DIM:      W2     = p; break;
            case P_DIM:           b2     = p; break;
            default: break;
        }
    }
    float* out = (float*)d_out;

    // Unconditional every call (no static guards — harness contract).
    cudaFuncSetAttribute(k_decode, cudaFuncAttributeMaxDynamicSharedMemorySize, SMEM_BYTES);

    k_hidden<<<M_ROWS / 8, 320>>>(digits, styles, W_h, b_h, W1, b1);
    dim3 grid(P_DIM / NT, M_ROWS / RT);   // (96, 32)
    k_decode<<<grid, 256, SMEM_BYTES>>>(images, W2, b2, out);
}